// round 2
// baseline (speedup 1.0000x reference)
#include <cuda_runtime.h>

#define Bb 8
#define Tt 800
#define Cc 8
#define Ff 513
#define Aa 320
#define NSYS (Bb*Ff)

// ---------------- device scratch (no allocations allowed) ----------------
__device__ float2 g_psd_s[NSYS*64];
__device__ float2 g_psd_n[NSYS*64];
__device__ float  g_e[Bb*Cc];
__device__ float2 g_wsc[Bb*Cc*Ff];   // conj(ws), layout (b, c, f)

typedef unsigned long long u64;

__device__ __forceinline__ u64 pk2(float lo, float hi){
    u64 r; asm("mov.b64 %0, {%1, %2};" : "=l"(r) : "f"(lo), "f"(hi)); return r;
}
__device__ __forceinline__ void upk2(float &lo, float &hi, u64 v){
    asm("mov.b64 {%0, %1}, %2;" : "=f"(lo), "=f"(hi) : "l"(v));
}
__device__ __forceinline__ void fma2(u64 &d, u64 a, u64 b){
    asm("fma.rn.f32x2 %0, %1, %2, %0;" : "+l"(d) : "l"(a), "l"(b));
}

__device__ __forceinline__ float2 cmul(float2 a, float2 b){
    return make_float2(a.x*b.x - a.y*b.y, a.x*b.y + a.y*b.x);
}
__device__ __forceinline__ float2 csub(float2 a, float2 b){
    return make_float2(a.x - b.x, a.y - b.y);
}
__device__ __forceinline__ float2 cinv(float2 a){
    float d = 1.f/(a.x*a.x + a.y*a.y);
    return make_float2(a.x*d, -a.y*d);
}

// ---------------- K1: PSD (speech + noise) -------------------------------
// grid (65, 8), block 256, dyn smem = 8*800*2*4 = 51200 B
__global__ void psd_kernel(const float* __restrict__ dre,
                           const float* __restrict__ dimg,
                           const float* __restrict__ msk_s,
                           const float* __restrict__ msk_n)
{
    extern __shared__ float sm[];
    float* sm_ms = sm;              // [8][800]
    float* sm_mn = sm + 8*Tt;       // [8][800]
    __shared__ float inv_s[8], inv_n[8];

    const int tid = threadIdx.x;
    const int b  = blockIdx.y;
    const int f0 = blockIdx.x * 8;

    // ---- phase 1: mask mean over c, store to smem (coalesced over t) ----
    for (int idx = tid; idx < 8*Tt; idx += 256) {
        int fl = idx / Tt;
        int t  = idx - fl*Tt;
        int f  = f0 + fl; if (f >= Ff) f = Ff-1;
        const float* ps = msk_s + ((size_t)(b*Ff + f)*Cc)*Tt + t;
        const float* pn = msk_n + ((size_t)(b*Ff + f)*Cc)*Tt + t;
        float ss = 0.f, sn = 0.f;
        #pragma unroll
        for (int c = 0; c < Cc; c++) {
            ss += fmaxf(ps[c*Tt], 1e-6f);
            sn += fmaxf(pn[c*Tt], 1e-6f);
        }
        sm_ms[idx] = ss * 0.125f;
        sm_mn[idx] = sn * 0.125f;
    }
    __syncthreads();
    {   // per-f sums over t, one warp per f
        int w = tid >> 5, lane = tid & 31;
        float as = 0.f, an = 0.f;
        for (int t = lane; t < Tt; t += 32) { as += sm_ms[w*Tt + t]; an += sm_mn[w*Tt + t]; }
        #pragma unroll
        for (int o = 16; o > 0; o >>= 1) {
            as += __shfl_down_sync(0xffffffffu, as, o);
            an += __shfl_down_sync(0xffffffffu, an, o);
        }
        if (lane == 0) { inv_s[w] = 1.f/(as + 1e-15f); inv_n[w] = 1.f/(an + 1e-15f); }
    }
    __syncthreads();
    for (int idx = tid; idx < 8*Tt; idx += 256) {
        int fl = idx / Tt;
        sm_ms[idx] *= inv_s[fl];
        sm_mn[idx] *= inv_n[fl];
    }
    __syncthreads();

    // ---- phase 2: accumulate psd[c][e] (upper tri) with packed f32x2 ----
    const int fl   = tid & 7;
    const int tp   = tid >> 3;      // 0..31
    const int msel = tp & 1;        // 0 -> speech, 1 -> noise
    const int ts   = tp >> 1;       // 0..15
    int f = f0 + fl;
    const bool valid = f < Ff;
    const int fc = valid ? f : Ff-1;

    const float* basr = dre  + (size_t)b*Tt*Cc*Ff + fc;
    const float* basi = dimg + (size_t)b*Tt*Cc*Ff + fc;
    const float* msh = (msel == 0 ? sm_ms : sm_mn) + fl*Tt;

    u64 acc[36];
    #pragma unroll
    for (int i = 0; i < 36; i++) acc[i] = 0ULL;

    for (int t = ts; t < Tt; t += 16) {
        float m = msh[t];
        const float* pr = basr + (size_t)t*Cc*Ff;
        const float* pi = basi + (size_t)t*Cc*Ff;
        float xr[8], xi[8];
        u64 av[8], cv[8];
        #pragma unroll
        for (int c = 0; c < 8; c++) {
            xr[c] = pr[c*Ff]; xi[c] = pi[c*Ff];
            av[c] = pk2(xr[c], xi[c]);      // (xr, xi)
            cv[c] = pk2(xi[c], -xr[c]);     // (xi, -xr)
        }
        #pragma unroll
        for (int e = 0; e < 8; e++) {
            float bre = xr[e]*m, bie = xi[e]*m;
            u64 br = pk2(bre, bre), bi = pk2(bie, bie);
            #pragma unroll
            for (int c = 0; c <= e; c++) {
                int id = (e*(e+1))/2 + c;
                // psd[c][e] += m * x_c * conj(x_e)
                fma2(acc[id], av[c], br);
                fma2(acc[id], cv[c], bi);
            }
        }
    }

    __syncthreads();             // m buffers dead; reuse smem for reduction
    float2* red = (float2*)sm;   // [8 fl][2 mask][36]
    for (int w = 0; w < 32; w++) {
        if (tp == w) {
            float2* dst = red + (fl*2 + msel)*36;
            #pragma unroll
            for (int i = 0; i < 36; i++) {
                float lo, hi; upk2(lo, hi, acc[i]);
                if (w < 2) dst[i] = make_float2(lo, hi);
                else { dst[i].x += lo; dst[i].y += hi; }
            }
        }
        __syncthreads();
    }

    // expand Hermitian and write (8 fl x 2 mask x 64 entries = 1024)
    for (int idx = tid; idx < 1024; idx += 256) {
        int fl2 = idx >> 7;
        int rem = idx & 127;
        int mk  = rem >> 6;
        int ce  = rem & 63;
        int c   = ce >> 3, e = ce & 7;
        int ff  = f0 + fl2; if (ff >= Ff) continue;
        const float2* src = red + (fl2*2 + mk)*36;
        float2 v;
        if (c <= e) v = src[(e*(e+1))/2 + c];
        else { float2 u = src[(c*(c+1))/2 + e]; v = make_float2(u.x, -u.y); }
        float2* dstp = (mk == 0 ? g_psd_s : g_psd_n);
        dstp[(size_t)(b*Ff + ff)*64 + ce] = v;
    }
}

// ---------------- K2: attention MLP -> logits e[b,c] ---------------------
// grid 64 (b*8+c), block 320
__global__ void attn_kernel(const float* __restrict__ mlp_w,
                            const float* __restrict__ mlp_b,
                            const float* __restrict__ gvw,
                            const float* __restrict__ gvb)
{
    __shared__ float feat[Ff];
    __shared__ float red[Aa];
    const int tid = threadIdx.x;
    const int b = blockIdx.x >> 3;
    const int c = blockIdx.x & 7;

    for (int f = tid; f < Ff; f += Aa) {
        const float2* p = g_psd_s + (size_t)(b*Ff + f)*64 + c*8;
        float sr = 0.f, si = 0.f;
        #pragma unroll
        for (int e = 0; e < 8; e++) { float2 v = p[e]; sr += v.x; si += v.y; }
        float2 d = p[c]; sr -= d.x; si -= d.y;   // zero diagonal
        sr *= (1.f/7.f); si *= (1.f/7.f);
        feat[f] = sqrtf(sr*sr + si*si);
    }
    __syncthreads();

    float acc = mlp_b[tid];
    #pragma unroll 4
    for (int f = 0; f < Ff; f++) acc += feat[f] * mlp_w[(size_t)f*Aa + tid];
    red[tid] = tanhf(acc) * gvw[tid];
    __syncthreads();
    if (tid < 160) red[tid] += red[tid+160]; __syncthreads();
    if (tid <  80) red[tid] += red[tid+ 80]; __syncthreads();
    if (tid <  40) red[tid] += red[tid+ 40]; __syncthreads();
    if (tid <  20) red[tid] += red[tid+ 20]; __syncthreads();
    if (tid <  10) red[tid] += red[tid+ 10]; __syncthreads();
    if (tid == 0) {
        float s = 0.f;
        #pragma unroll
        for (int i = 0; i < 10; i++) s += red[i];
        g_e[b*8 + c] = s + gvb[0];
    }
}

// ---------------- K3: MVDR solve + softmax + ws --------------------------
// 8 threads per system, 32 systems per block
__global__ void solve_kernel()
{
    __shared__ float2 Ash[32][64];
    __shared__ float2 Ssh[32][64];
    const int tid = threadIdx.x;
    const int g = tid >> 3, r = tid & 7;
    int sys = blockIdx.x*32 + g;
    bool ok = sys < NSYS;
    int sc = ok ? sys : NSYS-1;
    int b = sc / Ff, f = sc - b*Ff;

    #pragma unroll
    for (int j = 0; j < 8; j++) {
        Ash[g][r*8+j] = g_psd_n[(size_t)sc*64 + r*8 + j];
        Ssh[g][r*8+j] = g_psd_s[(size_t)sc*64 + r*8 + j];
    }
    Ash[g][r*8+r].x += 1e-15f;

    // softmax(2*e[b,:]) — redundant per thread, trivial
    float u[8];
    {
        float mx = -1e30f;
        #pragma unroll
        for (int j = 0; j < 8; j++) { u[j] = 2.f*g_e[b*8+j]; mx = fmaxf(mx, u[j]); }
        float s = 0.f;
        #pragma unroll
        for (int j = 0; j < 8; j++) { u[j] = expf(u[j]-mx); s += u[j]; }
        float is = 1.f/s;
        #pragma unroll
        for (int j = 0; j < 8; j++) u[j] *= is;
    }
    __syncwarp();

    // forward elimination (Hermitian PD -> no pivoting)
    for (int k = 0; k < 7; k++) {
        float2 ip = cinv(Ash[g][k*8+k]);
        if (r > k) {
            float2 fac = cmul(Ash[g][r*8+k], ip);
            #pragma unroll
            for (int j = 0; j < 8; j++)
                Ash[g][r*8+j] = csub(Ash[g][r*8+j], cmul(fac, Ash[g][k*8+j]));
            #pragma unroll
            for (int j = 0; j < 8; j++)
                Ssh[g][r*8+j] = csub(Ssh[g][r*8+j], cmul(fac, Ssh[g][k*8+j]));
        }
        __syncwarp();
    }
    // back substitution (S becomes X = inv(psd_n) @ psd_s)
    for (int k = 7; k >= 0; k--) {
        if (r == k) {
            float2 ip = cinv(Ash[g][k*8+k]);
            #pragma unroll
            for (int j = 0; j < 8; j++)
                Ssh[g][k*8+j] = cmul(Ssh[g][k*8+j], ip);
        }
        __syncwarp();
        if (r < k) {
            float2 fac = Ash[g][r*8+k];
            #pragma unroll
            for (int j = 0; j < 8; j++)
                Ssh[g][r*8+j] = csub(Ssh[g][r*8+j], cmul(fac, Ssh[g][k*8+j]));
        }
        __syncwarp();
    }

    float2 tr = make_float2(1e-15f, 0.f);
    #pragma unroll
    for (int ci = 0; ci < 8; ci++) { float2 d = Ssh[g][ci*8+ci]; tr.x += d.x; tr.y += d.y; }
    float2 it = cinv(tr);
    float wr = 0.f, wi = 0.f;
    #pragma unroll
    for (int ci = 0; ci < 8; ci++) { float2 x = Ssh[g][r*8+ci]; wr += x.x*u[ci]; wi += x.y*u[ci]; }
    float2 w = cmul(make_float2(wr, wi), it);
    if (ok) g_wsc[(size_t)(b*8+r)*Ff + f] = make_float2(w.x, -w.y);   // store conj
}

// ---------------- K4: enhanced output ------------------------------------
// grid B*T, block 256
__global__ void enh_kernel(const float* __restrict__ dre,
                           const float* __restrict__ dimg,
                           float2* __restrict__ out)
{
    const int bt = blockIdx.x;
    const int b = bt / Tt;
    const float* pr = dre  + (size_t)bt*Cc*Ff;
    const float* pi = dimg + (size_t)bt*Cc*Ff;
    for (int f = threadIdx.x; f < Ff; f += 256) {
        float er = 0.f, ei = 0.f;
        #pragma unroll
        for (int c = 0; c < 8; c++) {
            float dr = pr[c*Ff + f];
            float di = pi[c*Ff + f];
            float2 w = g_wsc[(size_t)(b*8+c)*Ff + f];   // = conj(ws)
            er += w.x*dr - w.y*di;
            ei += w.x*di + w.y*dr;
        }
        out[(size_t)bt*Ff + f] = make_float2(er, ei);
    }
}

// ---------------- launch --------------------------------------------------
extern "C" void kernel_launch(void* const* d_in, const int* in_sizes, int n_in,
                              void* d_out, int out_size)
{
    const float* dre   = (const float*)d_in[0];
    const float* dimg  = (const float*)d_in[1];
    const float* ms    = (const float*)d_in[2];
    const float* mn    = (const float*)d_in[3];
    const float* mlp_w = (const float*)d_in[4];
    const float* mlp_b = (const float*)d_in[5];
    const float* gvw   = (const float*)d_in[6];
    const float* gvb   = (const float*)d_in[7];
    (void)in_sizes; (void)n_in; (void)out_size;

    cudaFuncSetAttribute(psd_kernel, cudaFuncAttributeMaxDynamicSharedMemorySize, 8*Tt*2*4);

    psd_kernel<<<dim3((Ff+7)/8, Bb), 256, 8*Tt*2*4>>>(dre, dimg, ms, mn);
    attn_kernel<<<Bb*Cc, Aa>>>(mlp_w, mlp_b, gvw, gvb);
    solve_kernel<<<(NSYS+31)/32, 256>>>();
    enh_kernel<<<Bb*Tt, 256>>>(dre, dimg, (float2*)d_out);
}